// round 10
// baseline (speedup 1.0000x reference)
#include <cuda_runtime.h>
#include <cstddef>
#include <cstdint>

// Problem constants
#define BATCH 32
#define NTOK  4900
#define DMODEL 256
#define HEADS 4
#define DH 64
#define WIN 49
#define RATE 5
#define NSEG 20
#define MROWS (BATCH*NTOK)
#define GK 256

// smem layout (words):
//   Qs   : uint32 tf32 q, 64 x 260                     [0      .. 16640)
//   EsAt : float, 64 x 260  (emb window, later att out)[16640  .. 33280)
//   WsQt : union — Ws 2 x (256x36) float  |  Qt 256x68 [33280  .. 51712)
#define QS_OFF   0
#define ESAT_OFF 16640
#define WSQT_OFF 33280
#define SMEM_WORDS 51712
#define QSTR 260
#define WSTR 36
#define TSTR 68
#define WS_STAGE 9216   // 256*36

__device__ __forceinline__ uint32_t to_tf32(float x) {
    uint32_t y;
    asm("cvt.rna.tf32.f32 %0, %1;" : "=r"(y) : "f"(x));
    return y;
}

__device__ __forceinline__ void mma_tf32_r(float* c,
                                           uint32_t a0, uint32_t a1, uint32_t a2, uint32_t a3,
                                           uint32_t b0, uint32_t b1) {
    asm volatile(
        "mma.sync.aligned.m16n8k8.row.col.f32.tf32.tf32.f32 "
        "{%0,%1,%2,%3}, {%4,%5,%6,%7}, {%8,%9}, {%0,%1,%2,%3};\n"
        : "+f"(c[0]), "+f"(c[1]), "+f"(c[2]), "+f"(c[3])
        : "r"(a0), "r"(a1), "r"(a2), "r"(a3), "r"(b0), "r"(b1));
}

// GEMM mainloop: A resident in smem (64 x 256 fp32, row stride QSTR),
// weights streamed from global (L2-resident) via 2-stage cp.async.
// Warp tile 64x32 (wn = warp id 0..7 -> 256 cols), accum c[4][4][4].
// NOTE: A gather advances kc*32 along K (this was the R9 bug).
__device__ __forceinline__ void proj_gemm(const float* __restrict__ W,
                                          const float* Asm, float* Ws,
                                          float c[4][4][4],
                                          int tid, int wn, int qd, int qq) {
    #pragma unroll
    for (int i = 0; i < 4; i++)
        #pragma unroll
        for (int j = 0; j < 4; j++)
            #pragma unroll
            for (int r = 0; r < 4; r++) c[i][j][r] = 0.f;

    auto issueW = [&](int stage, int kc) {
        float* Wd = Ws + stage * WS_STAGE;
        #pragma unroll
        for (int l = 0; l < 8; l++) {
            int i2 = l * 256 + tid;
            int n  = i2 >> 3;
            int kq = i2 & 7;
            uint32_t d = (uint32_t)__cvta_generic_to_shared(&Wd[n * WSTR + kq * 4]);
            const float* s = W + (size_t)n * GK + kc * 32 + kq * 4;
            asm volatile("cp.async.cg.shared.global [%0], [%1], 16;\n" :: "r"(d), "l"(s));
        }
        asm volatile("cp.async.commit_group;\n");
    };

    issueW(0, 0);
    const int aRow = qd;

    #pragma unroll 1
    for (int kc = 0; kc < 8; kc++) {
        const int cur = kc & 1;
        if (kc < 7) {
            issueW(cur ^ 1, kc + 1);
            asm volatile("cp.async.wait_group 1;\n");
        } else {
            asm volatile("cp.async.wait_group 0;\n");
        }
        __syncthreads();

        const float* Wc = Ws + cur * WS_STAGE;
        #pragma unroll
        for (int ks = 0; ks < 4; ks++) {
            uint32_t af[4][4];
            #pragma unroll
            for (int i = 0; i < 4; i++) {
                const float* p0 = &Asm[(aRow + i * 16) * QSTR + kc * 32 + ks * 8 + qq];
                af[i][0] = to_tf32(p0[0]);
                af[i][2] = to_tf32(p0[4]);
                af[i][1] = to_tf32(p0[8 * QSTR]);
                af[i][3] = to_tf32(p0[8 * QSTR + 4]);
            }
            uint32_t bf[4][2];
            #pragma unroll
            for (int j = 0; j < 4; j++) {
                const float* pb = &Wc[(wn * 32 + j * 8 + qd) * WSTR + ks * 8 + qq];
                bf[j][0] = to_tf32(pb[0]);
                bf[j][1] = to_tf32(pb[4]);
            }
            #pragma unroll
            for (int i = 0; i < 4; i++)
                #pragma unroll
                for (int j = 0; j < 4; j++)
                    mma_tf32_r(c[i][j], af[i][0], af[i][1], af[i][2], af[i][3],
                               bf[j][0], bf[j][1]);
        }
        __syncthreads();
    }
}

// ---------------------------------------------------------------------------
// Fused kernel: one block per (b, g, r); proj1 -> 4x windowed attention ->
// proj2, all in shared memory. DRAM touches: emb in, out out.
// ---------------------------------------------------------------------------
__global__ __launch_bounds__(256)
void fused_kernel(const float* __restrict__ emb,
                  const float* __restrict__ Wq, const float* __restrict__ bq,
                  const float* __restrict__ Wo, const float* __restrict__ bo,
                  float* __restrict__ outp) {
    extern __shared__ float smem[];
    uint32_t* Qs = reinterpret_cast<uint32_t*>(smem + QS_OFF);
    float*    Es = smem + ESAT_OFF;            // emb window, later att output
    float*    Ws = smem + WSQT_OFF;            // weight stages (proj phases)
    uint32_t* Qt = reinterpret_cast<uint32_t*>(smem + WSQT_OFF);  // attn phase

    const int idx = blockIdx.x;
    const int r  = idx % RATE;
    const int gg = (idx / RATE) % NSEG;
    const int b  = idx / (RATE * NSEG);
    const size_t rowBase = (size_t)b * NTOK + (size_t)gg * (WIN * RATE) + r;
    const float* ebase = emb + rowBase * DMODEL;   // token i at + i*RATE*DMODEL
    float* obase = outp + rowBase * DMODEL;

    const int tid  = threadIdx.x;
    const int warp = tid >> 5, lane = tid & 31;
    const int qd = lane >> 2, qq = lane & 3;

    // ---- Phase A: stage emb window (49 x 256) + zero pad rows 49..63 ----
    for (int t = tid; t < WIN * 64; t += 256) {
        int row = t >> 6, c4 = t & 63;
        uint32_t d = (uint32_t)__cvta_generic_to_shared(&Es[row * QSTR + c4 * 4]);
        const float* s = ebase + (size_t)row * (RATE * DMODEL) + c4 * 4;
        asm volatile("cp.async.cg.shared.global [%0], [%1], 16;\n" :: "r"(d), "l"(s));
    }
    asm volatile("cp.async.commit_group;\n");
    for (int t = tid; t < 15 * QSTR; t += 256)
        Es[WIN * QSTR + t] = 0.f;   // rows 49..63

    float c[4][4][4];

    // ---- Phase B: proj1  q = emb @ Wq^T + bq  ->  Qs (tf32) + Qt (tf32^T) ----
    proj_gemm(Wq, Es, Ws, c, tid, warp, qd, qq);
    // epilogue (Ws now dead -> Qt may be written; loop ended with __syncthreads)
    #pragma unroll
    for (int j = 0; j < 4; j++) {
        int col0 = warp * 32 + j * 8 + 2 * qq;
        float b0 = bq[col0], b1 = bq[col0 + 1];
        #pragma unroll
        for (int i = 0; i < 4; i++) {
            int r0 = i * 16 + qd, r1 = r0 + 8;
            uint32_t u00 = to_tf32(c[i][j][0] + b0);
            uint32_t u01 = to_tf32(c[i][j][1] + b1);
            uint32_t u10 = to_tf32(c[i][j][2] + b0);
            uint32_t u11 = to_tf32(c[i][j][3] + b1);
            *reinterpret_cast<uint2*>(&Qs[r0 * QSTR + col0]) = make_uint2(u00, u01);
            *reinterpret_cast<uint2*>(&Qs[r1 * QSTR + col0]) = make_uint2(u10, u11);
            Qt[col0 * TSTR + r0]       = u00;
            Qt[(col0 + 1) * TSTR + r0] = u01;
            Qt[col0 * TSTR + r1]       = u10;
            Qt[(col0 + 1) * TSTR + r1] = u11;
        }
    }
    __syncthreads();

    // ---- Phase C: attention per head; warp-group (4 warps) per head, 2 passes
    const int wg = warp >> 2, wlocal = warp & 3;
    const int mrow = wlocal * 16;
    const float scale = 0.125f;
    const float NEG = __int_as_float(0xff800000);

    #pragma unroll 1
    for (int hp = 0; hp < 2; hp++) {
        const int h = hp * 2 + wg;
        const int hb = h * 64;

        // scores = X X^T (7 n-tiles: j < 56)
        float sc[7][4];
        #pragma unroll
        for (int nt = 0; nt < 7; nt++)
            #pragma unroll
            for (int k = 0; k < 4; k++) sc[nt][k] = 0.f;

        #pragma unroll
        for (int ks = 0; ks < 8; ks++) {
            uint32_t a0 = Qs[(mrow + qd) * QSTR + hb + ks * 8 + qq];
            uint32_t a1 = Qs[(mrow + qd + 8) * QSTR + hb + ks * 8 + qq];
            uint32_t a2 = Qs[(mrow + qd) * QSTR + hb + ks * 8 + qq + 4];
            uint32_t a3 = Qs[(mrow + qd + 8) * QSTR + hb + ks * 8 + qq + 4];
            #pragma unroll
            for (int nt = 0; nt < 7; nt++) {
                uint32_t b0 = Qs[(nt * 8 + qd) * QSTR + hb + ks * 8 + qq];
                uint32_t b1 = Qs[(nt * 8 + qd) * QSTR + hb + ks * 8 + qq + 4];
                mma_tf32_r(sc[nt], a0, a1, a2, a3, b0, b1);
            }
        }

        // mask + softmax in fragments (pad cols j>=49 hold bias garbage -> NEG)
        float m0 = NEG, m1 = NEG;
        #pragma unroll
        for (int nt = 0; nt < 7; nt++)
            #pragma unroll
            for (int par = 0; par < 2; par++) {
                int j = nt * 8 + 2 * qq + par;
                float v0 = (j < WIN) ? sc[nt][par] * scale : NEG;
                float v1 = (j < WIN) ? sc[nt][par + 2] * scale : NEG;
                sc[nt][par] = v0;
                sc[nt][par + 2] = v1;
                m0 = fmaxf(m0, v0);
                m1 = fmaxf(m1, v1);
            }
        m0 = fmaxf(m0, __shfl_xor_sync(0xffffffffu, m0, 1));
        m0 = fmaxf(m0, __shfl_xor_sync(0xffffffffu, m0, 2));
        m1 = fmaxf(m1, __shfl_xor_sync(0xffffffffu, m1, 1));
        m1 = fmaxf(m1, __shfl_xor_sync(0xffffffffu, m1, 2));

        float s0 = 0.f, s1 = 0.f;
        #pragma unroll
        for (int nt = 0; nt < 7; nt++)
            #pragma unroll
            for (int par = 0; par < 2; par++) {
                float e0 = __expf(sc[nt][par] - m0);
                float e1 = __expf(sc[nt][par + 2] - m1);
                sc[nt][par] = e0;
                sc[nt][par + 2] = e1;
                s0 += e0;
                s1 += e1;
            }
        s0 += __shfl_xor_sync(0xffffffffu, s0, 1);
        s0 += __shfl_xor_sync(0xffffffffu, s0, 2);
        s1 += __shfl_xor_sync(0xffffffffu, s1, 1);
        s1 += __shfl_xor_sync(0xffffffffu, s1, 2);
        float inv0 = 1.f / s0, inv1 = 1.f / s1;

        // PV (7 k-steps), B from Qt; tokens 49..55 have P==0 exactly.
        float o[8][4];
        #pragma unroll
        for (int nt = 0; nt < 8; nt++)
            #pragma unroll
            for (int k = 0; k < 4; k++) o[nt][k] = 0.f;

        const int srcA = (lane & ~3) + (qq >> 1);
        const bool odd = (qq & 1);

        #pragma unroll
        for (int ks = 0; ks < 7; ks++) {
            float v0 = __shfl_sync(0xffffffffu, sc[ks][0], srcA);
            float v1 = __shfl_sync(0xffffffffu, sc[ks][1], srcA);
            float v2 = __shfl_sync(0xffffffffu, sc[ks][2], srcA);
            float v3 = __shfl_sync(0xffffffffu, sc[ks][3], srcA);
            float w0 = __shfl_sync(0xffffffffu, sc[ks][0], srcA + 2);
            float w1 = __shfl_sync(0xffffffffu, sc[ks][1], srcA + 2);
            float w2 = __shfl_sync(0xffffffffu, sc[ks][2], srcA + 2);
            float w3 = __shfl_sync(0xffffffffu, sc[ks][3], srcA + 2);
            uint32_t a0 = to_tf32(odd ? v1 : v0);
            uint32_t a1 = to_tf32(odd ? v3 : v2);
            uint32_t a2 = to_tf32(odd ? w1 : w0);
            uint32_t a3 = to_tf32(odd ? w3 : w2);
            #pragma unroll
            for (int nt = 0; nt < 8; nt++) {
                uint32_t b0 = Qt[(hb + nt * 8 + qd) * TSTR + ks * 8 + qq];
                uint32_t b1 = Qt[(hb + nt * 8 + qd) * TSTR + ks * 8 + qq + 4];
                mma_tf32_r(o[nt], a0, a1, a2, a3, b0, b1);
            }
        }

        // write normalized rows into At (= Es region); pad rows stay zero
        const int r0 = mrow + qd, r1 = r0 + 8;
        #pragma unroll
        for (int nt = 0; nt < 8; nt++) {
            int col = hb + nt * 8 + 2 * qq;
            if (r0 < WIN) {
                float2 v = {o[nt][0] * inv0, o[nt][1] * inv0};
                *reinterpret_cast<float2*>(&Es[r0 * QSTR + col]) = v;
            }
            if (r1 < WIN) {
                float2 v = {o[nt][2] * inv1, o[nt][3] * inv1};
                *reinterpret_cast<float2*>(&Es[r1 * QSTR + col]) = v;
            }
        }
    }
    __syncthreads();   // At complete; Qt no longer needed -> Ws may be reused

    // ---- Phase D: proj2  out = At @ Wo^T + bo  ->  gmem ----
    proj_gemm(Wo, Es, Ws, c, tid, warp, qd, qq);
    #pragma unroll
    for (int j = 0; j < 4; j++) {
        int col0 = warp * 32 + j * 8 + 2 * qq;
        float b0 = bo[col0], b1 = bo[col0 + 1];
        #pragma unroll
        for (int i = 0; i < 4; i++) {
            int r0 = i * 16 + qd, r1 = r0 + 8;
            if (r0 < WIN) {
                float2 v = {c[i][j][0] + b0, c[i][j][1] + b1};
                *reinterpret_cast<float2*>(obase + (size_t)r0 * (RATE * DMODEL) + col0) = v;
            }
            if (r1 < WIN) {
                float2 v = {c[i][j][2] + b0, c[i][j][3] + b1};
                *reinterpret_cast<float2*>(obase + (size_t)r1 * (RATE * DMODEL) + col0) = v;
            }
        }
    }
}

// ---------------------------------------------------------------------------
// Launch: single fused kernel
// ---------------------------------------------------------------------------
extern "C" void kernel_launch(void* const* d_in, const int* in_sizes, int n_in,
                              void* d_out, int out_size) {
    const float* emb = (const float*)d_in[0];
    const float* Wq  = (const float*)d_in[1];
    const float* bq  = (const float*)d_in[2];
    const float* Wo  = (const float*)d_in[3];
    const float* bo  = (const float*)d_in[4];
    float* outp = (float*)d_out;

    const int smemBytes = SMEM_WORDS * 4;   // 206848
    static bool attrSet = false;
    if (!attrSet) {
        cudaFuncSetAttribute(fused_kernel,
                             cudaFuncAttributeMaxDynamicSharedMemorySize, smemBytes);
        attrSet = true;
    }

    fused_kernel<<<BATCH * NSEG * RATE, 256, smemBytes>>>(emb, Wq, bq, Wo, bo, outp);
}